// round 12
// baseline (speedup 1.0000x reference)
#include <cuda_runtime.h>
#include <cuda_fp16.h>
#include <cstdint>

#define NTOK 4096
#define CDIM 256
#define HEADS 8
#define QSCALE (0.17677669529663687f * 1.4426950408889634f)
#define MNEG (-30.0f)   // masked score: 2^-30 flushes to 0 in f16

// scratch (allocation-free rule: device globals)
__device__ uint32_t g_mask[NTOK * (NTOK / 32)];    // packed adj bitmask, 2 MB
__device__ uint16_t g_xhi[NTOK * CDIM],  g_xlo[NTOK * CDIM];        // x split
__device__ uint16_t g_wqh[3 * CDIM * CDIM], g_wql[3 * CDIM * CDIM]; // w_qkv split
__device__ uint16_t g_wph[CDIM * CDIM],  g_wpl[CDIM * CDIM];        // w_proj split
__device__ uint16_t g_kvh[NTOK * 3 * CDIM];        // qkv fp16 (q pre-scaled)
__device__ uint16_t g_ath[NTOK * CDIM],  g_atl[NTOK * CDIM];        // attn out split

// ---------------------------------------------------------------------------
// helpers
// ---------------------------------------------------------------------------
__device__ __forceinline__ uint32_t pkh(float x, float y) {  // f16x2(lo=x,hi=y)
    uint32_t r;
    asm("cvt.rn.f16x2.f32 %0, %1, %2;" : "=r"(r) : "f"(y), "f"(x));
    return r;
}
__device__ __forceinline__ uint32_t hex2(uint32_t x) {       // 2^x per f16 lane
    uint32_t y;
    asm("ex2.approx.f16x2 %0, %1;" : "=r"(y) : "r"(x));
    return y;
}
__device__ __forceinline__ void splith(float x, float y, uint32_t& hi, uint32_t& lo) {
    uint32_t h = pkh(x, y);
    float xh, yh;
    asm("{ .reg .f16 a,b;\n  mov.b32 {a,b}, %2;\n  cvt.f32.f16 %0, a;\n  cvt.f32.f16 %1, b; }"
        : "=f"(xh), "=f"(yh) : "r"(h));
    hi = h;
    lo = pkh(x - xh, y - yh);
}
__device__ __forceinline__ uint32_t prmt(uint32_t a, uint32_t b, uint32_t sel) {
    uint32_t r;
    asm("prmt.b32 %0, %1, %2, %3;" : "=r"(r) : "r"(a), "r"(b), "r"(sel));
    return r;
}
__device__ __forceinline__ uint32_t smem_u32(const void* p) {
    uint32_t a;
    asm("{ .reg .u64 t; cvta.to.shared.u64 t, %1; cvt.u32.u64 %0, t; }" : "=r"(a) : "l"(p));
    return a;
}
// m16n8k16 fp16 MMA, f32 accumulate (A row-major, B col-major)
__device__ __forceinline__ void mma_f16(float* c, const uint32_t* a,
                                        uint32_t b0, uint32_t b1) {
    asm volatile(
        "mma.sync.aligned.m16n8k16.row.col.f32.f16.f16.f32 "
        "{%0,%1,%2,%3}, {%4,%5,%6,%7}, {%8,%9}, {%0,%1,%2,%3};"
        : "+f"(c[0]), "+f"(c[1]), "+f"(c[2]), "+f"(c[3])
        : "r"(a[0]), "r"(a[1]), "r"(a[2]), "r"(a[3]), "r"(b0), "r"(b1));
}
__device__ __forceinline__ void ldsm4(uint32_t* r, uint32_t a) {
    asm volatile("ldmatrix.sync.aligned.m8n8.x4.shared.b16 {%0,%1,%2,%3}, [%4];"
        : "=r"(r[0]), "=r"(r[1]), "=r"(r[2]), "=r"(r[3]) : "r"(a));
}
__device__ __forceinline__ void ldsm2(uint32_t* r, uint32_t a) {
    asm volatile("ldmatrix.sync.aligned.m8n8.x2.shared.b16 {%0,%1}, [%2];"
        : "=r"(r[0]), "=r"(r[1]) : "r"(a));
}

// ---------------------------------------------------------------------------
// pack adj into bitmask
// ---------------------------------------------------------------------------
__global__ __launch_bounds__(256) void pack_mask(
    const int* __restrict__ adj, uint32_t* __restrict__ mb)
{
    int w = blockIdx.x * blockDim.x + threadIdx.x;
    const int4* p = (const int4*)(adj + (size_t)w * 32);
    uint32_t bits = 0;
#pragma unroll
    for (int i = 0; i < 8; i++) {
        int4 a = p[i];
        bits |= (a.x > 0 ? 1u : 0u) << (4 * i + 0);
        bits |= (a.y > 0 ? 1u : 0u) << (4 * i + 1);
        bits |= (a.z > 0 ? 1u : 0u) << (4 * i + 2);
        bits |= (a.w > 0 ? 1u : 0u) << (4 * i + 3);
    }
    mb[w] = bits;
}

// ---------------------------------------------------------------------------
// pack f32 -> fp16 hi + fp16 lo residual (4 floats per thread)
// ---------------------------------------------------------------------------
__global__ __launch_bounds__(256) void pack_halves(
    const float* __restrict__ src, uint16_t* __restrict__ hi,
    uint16_t* __restrict__ lo)
{
    int i = blockIdx.x * blockDim.x + threadIdx.x;
    float4 f = ((const float4*)src)[i];
    uint32_t h01, l01, h23, l23;
    splith(f.x, f.y, h01, l01);
    splith(f.z, f.w, h23, l23);
    ((uint2*)hi)[i] = make_uint2(h01, h23);
    ((uint2*)lo)[i] = make_uint2(l01, l23);
}

// ---------------------------------------------------------------------------
// Split-fp16 tensor-core GEMM core (3 terms). Block tile 128x64, 256 threads,
// warp tile 32x32, BK=32.
// ---------------------------------------------------------------------------
#define GEMM_BODY                                                              \
    __shared__ uint16_t sA[2][128 * 40];                                       \
    __shared__ uint16_t sB[2][64 * 40];                                        \
    const int tid = threadIdx.x;                                               \
    const int w    = tid >> 5;                                                 \
    const int lane = tid & 31;                                                 \
    const int g    = lane >> 2;                                                \
    const int t    = lane & 3;                                                 \
    const int wm   = w >> 1;                                                   \
    const int wn   = w & 1;                                                    \
    const int m0 = blockIdx.y << 7;                                            \
    const int n0 = blockIdx.x << 6;                                            \
    const int ar = tid >> 1, ac = (tid & 1) * 16;                              \
    const int br = tid >> 2, bc = (tid & 3) * 8;                               \
    const uint16_t* Ah = Ahi + (size_t)(m0 + ar) * K + ac;                     \
    const uint16_t* Al = Alo + (size_t)(m0 + ar) * K + ac;                     \
    const uint16_t* Bh = Bhi + (size_t)(n0 + br) * K + bc;                     \
    const uint16_t* Bl = Blo + (size_t)(n0 + br) * K + bc;                     \
    float c[2][4][4];                                                          \
    _Pragma("unroll")                                                          \
    for (int i = 0; i < 2; i++)                                                \
        _Pragma("unroll")                                                      \
        for (int n = 0; n < 4; n++)                                            \
            _Pragma("unroll")                                                  \
            for (int j = 0; j < 4; j++) c[i][n][j] = 0.0f;                     \
    uint4 pah0 = ((const uint4*)Ah)[0], pah1 = ((const uint4*)Ah)[1];          \
    uint4 pal0 = ((const uint4*)Al)[0], pal1 = ((const uint4*)Al)[1];          \
    uint4 pbh  = ((const uint4*)Bh)[0];                                        \
    uint4 pbl  = ((const uint4*)Bl)[0];                                        \
    for (int k0 = 0; k0 < K; k0 += 32) {                                       \
        __syncthreads();                                                       \
        *(uint4*)&sA[0][ar * 40 + ac]     = pah0;                              \
        *(uint4*)&sA[0][ar * 40 + ac + 8] = pah1;                              \
        *(uint4*)&sA[1][ar * 40 + ac]     = pal0;                              \
        *(uint4*)&sA[1][ar * 40 + ac + 8] = pal1;                              \
        *(uint4*)&sB[0][br * 40 + bc]     = pbh;                               \
        *(uint4*)&sB[1][br * 40 + bc]     = pbl;                               \
        __syncthreads();                                                       \
        if (k0 + 32 < K) {                                                     \
            pah0 = ((const uint4*)(Ah + k0 + 32))[0];                          \
            pah1 = ((const uint4*)(Ah + k0 + 32))[1];                          \
            pal0 = ((const uint4*)(Al + k0 + 32))[0];                          \
            pal1 = ((const uint4*)(Al + k0 + 32))[1];                          \
            pbh  = ((const uint4*)(Bh + k0 + 32))[0];                          \
            pbl  = ((const uint4*)(Bl + k0 + 32))[0];                          \
        }                                                                      \
        _Pragma("unroll")                                                      \
        for (int s = 0; s < 2; s++) {                                          \
            uint32_t ah[2][4], al[2][4];                                       \
            _Pragma("unroll")                                                  \
            for (int i = 0; i < 2; i++) {                                      \
                const int r0 = (wm * 32 + i * 16 + g) * 40 + 16 * s + 2 * t;   \
                const int r1 = r0 + 8 * 40;                                    \
                ah[i][0] = *(const uint32_t*)&sA[0][r0];                       \
                ah[i][1] = *(const uint32_t*)&sA[0][r1];                       \
                ah[i][2] = *(const uint32_t*)&sA[0][r0 + 8];                   \
                ah[i][3] = *(const uint32_t*)&sA[0][r1 + 8];                   \
                al[i][0] = *(const uint32_t*)&sA[1][r0];                       \
                al[i][1] = *(const uint32_t*)&sA[1][r1];                       \
                al[i][2] = *(const uint32_t*)&sA[1][r0 + 8];                   \
                al[i][3] = *(const uint32_t*)&sA[1][r1 + 8];                   \
            }                                                                  \
            _Pragma("unroll")                                                  \
            for (int n = 0; n < 4; n++) {                                      \
                const int ro = (wn * 32 + n * 8 + g) * 40 + 16 * s + 2 * t;    \
                uint32_t bh0 = *(const uint32_t*)&sB[0][ro];                   \
                uint32_t bh1 = *(const uint32_t*)&sB[0][ro + 8];               \
                uint32_t bl0 = *(const uint32_t*)&sB[1][ro];                   \
                uint32_t bl1 = *(const uint32_t*)&sB[1][ro + 8];               \
                _Pragma("unroll")                                              \
                for (int i = 0; i < 2; i++) {                                  \
                    mma_f16(c[i][n], ah[i], bh0, bh1);                         \
                    mma_f16(c[i][n], ah[i], bl0, bl1);                         \
                    mma_f16(c[i][n], al[i], bh0, bh1);                         \
                }                                                              \
            }                                                                  \
        }                                                                      \
    }

__global__ __launch_bounds__(256) void gemm_tc(
    const uint16_t* __restrict__ Ahi, const uint16_t* __restrict__ Alo,
    const uint16_t* __restrict__ Bhi, const uint16_t* __restrict__ Blo,
    const float* __restrict__ bias, float* __restrict__ Y,
    int M, int Nn, int K)
{
    GEMM_BODY
#pragma unroll
    for (int n = 0; n < 4; n++) {
        const int col = n0 + wn * 32 + n * 8 + 2 * t;
        float b0 = 0.f, b1 = 0.f;
        if (bias) { b0 = bias[col]; b1 = bias[col + 1]; }
#pragma unroll
        for (int i = 0; i < 2; i++) {
            const int row0 = m0 + wm * 32 + i * 16 + g;
            float2 v0; v0.x = c[i][n][0] + b0; v0.y = c[i][n][1] + b1;
            float2 v1; v1.x = c[i][n][2] + b0; v1.y = c[i][n][3] + b1;
            *(float2*)(Y + (size_t)row0 * Nn + col) = v0;
            *(float2*)(Y + (size_t)(row0 + 8) * Nn + col) = v1;
        }
    }
}

// hi-only fp16 output; q columns (col < 256) scaled by QSCALE
__global__ __launch_bounds__(256) void gemm_tch(
    const uint16_t* __restrict__ Ahi, const uint16_t* __restrict__ Alo,
    const uint16_t* __restrict__ Bhi, const uint16_t* __restrict__ Blo,
    uint16_t* __restrict__ Yh, int M, int Nn, int K)
{
    GEMM_BODY
    const float sc = (n0 < 256) ? QSCALE : 1.0f;
#pragma unroll
    for (int n = 0; n < 4; n++) {
        const int col = n0 + wn * 32 + n * 8 + 2 * t;
#pragma unroll
        for (int i = 0; i < 2; i++) {
            const int row0 = m0 + wm * 32 + i * 16 + g;
            *(uint32_t*)&Yh[(size_t)row0 * Nn + col] =
                pkh(c[i][n][0] * sc, c[i][n][1] * sc);
            *(uint32_t*)&Yh[(size_t)(row0 + 8) * Nn + col] =
                pkh(c[i][n][2] * sc, c[i][n][3] * sc);
        }
    }
}

// ---------------------------------------------------------------------------
// Tensor-core flash attention, pure fp16, fixed-zero softmax reference.
// Block: 64 q-rows x 1 head, 128 threads, occupancy 4 (single wave).
// New in R12:
//  - exp via ex2.approx.f16x2 on the packed P pairs (MUFU ops halved)
//  - l computed by an extra ones-column MMA (V^T dh-row 32 == 1.0): exact
//    f32 accumulation, removes the per-tile FADD chain and shfl-adds
//  - ping-pong K/V smem buffers: ONE __syncthreads per tile
// ---------------------------------------------------------------------------
#define KBUF (64 * 40 * 2)   // bytes per K buffer
#define VBUF (40 * 72 * 2)   // bytes per V buffer

__global__ __launch_bounds__(128, 4) void attn_tc(
    const uint16_t* __restrict__ qkv, const uint32_t* __restrict__ mb,
    uint16_t* __restrict__ outh, uint16_t* __restrict__ outl)
{
    __shared__ __align__(16) uint16_t Khi[2][64 * 40];
    __shared__ __align__(16) uint16_t Vthi[2][40 * 72];

    const int tid  = threadIdx.x;
    const int w    = tid >> 5;
    const int lane = tid & 31;
    const int g    = lane >> 2;
    const int t    = lane & 3;
    const int h    = blockIdx.y;
    const int q0   = blockIdx.x << 6;
    const int rA   = q0 + w * 16 + g;
    const int rB   = rA + 8;

    // ldmatrix per-lane addressing (quadrant layout)
    const int rowadd = ((lane >> 4) & 1) * 8 + (lane & 7);
    const int coladd = ((lane >> 3) & 1) * 8;
    const uint32_t kaddr = smem_u32(Khi)  + (uint32_t)(rowadd * 40 + coladd) * 2u;
    const uint32_t vaddr = smem_u32(Vthi) + (uint32_t)(rowadd * 72 + coladd) * 2u;
    // l-tile address (rows 32..39; x2 uses lanes 0..15, keep all lanes in-bounds)
    const uint32_t laddr = smem_u32(Vthi) +
        (uint32_t)(((32 + (lane & 7)) * 72) + coladd) * 2u;

    // ---- Q fragments: direct packed loads (scale already folded) ----
    uint32_t qa[2][4];
#pragma unroll
    for (int s = 0; s < 2; s++) {
        const size_t bA = (size_t)rA * 768 + h * 32 + 16 * s + 2 * t;
        const size_t bB = (size_t)rB * 768 + h * 32 + 16 * s + 2 * t;
        qa[s][0] = *(const uint32_t*)&qkv[bA];
        qa[s][1] = *(const uint32_t*)&qkv[bB];
        qa[s][2] = *(const uint32_t*)&qkv[bA + 8];
        qa[s][3] = *(const uint32_t*)&qkv[bB + 8];
    }

    float o[4][4];
    float o4[4];
#pragma unroll
    for (int n = 0; n < 4; n++) {
        o4[n] = 0.0f;
#pragma unroll
        for (int i = 0; i < 4; i++) o[n][i] = 0.0f;
    }

    // loaders
    const int klr = tid >> 1;
    const int klc = (tid & 1) * 16;
    const uint16_t* kbg = qkv + (size_t)klr * 768 + 256 + h * 32 + klc;
    const int vj = tid >> 2;
    const int vc = (tid & 3) * 8;
    const uint16_t* vbg = qkv + (size_t)(2 * vj) * 768 + 512 + h * 32 + vc;

    // ones/zero rows (32..39) of BOTH V buffers, once
    for (int i = tid; i < 2 * 8 * 72; i += 128) {
        const int buf = (i >= 8 * 72) ? 1 : 0;
        const int j = i - buf * 8 * 72;
        const int r = 32 + j / 72;
        Vthi[buf][r * 72 + (j % 72)] = (r == 32) ? (uint16_t)0x3C00 : (uint16_t)0;
    }

    uint4 kr0, kr1, va, vb;
    // tile 0 -> buf 0
    {
        kr0 = ((const uint4*)kbg)[0];
        kr1 = ((const uint4*)kbg)[1];
        va  = *(const uint4*)vbg;
        vb  = *(const uint4*)(vbg + 768);
        *(uint4*)&Khi[0][klr * 40 + klc]     = kr0;
        *(uint4*)&Khi[0][klr * 40 + klc + 8] = kr1;
        const uint32_t aw[4] = {va.x, va.y, va.z, va.w};
        const uint32_t bw[4] = {vb.x, vb.y, vb.z, vb.w};
#pragma unroll
        for (int d = 0; d < 8; d++) {
            uint32_t x = prmt(aw[d >> 1], bw[d >> 1], (d & 1) ? 0x7632u : 0x5410u);
            *(uint32_t*)&Vthi[0][(vc + d) * 72 + 2 * vj] = x;
        }
    }
    // tile 1 -> regs
    {
        const size_t off = (size_t)64 * 768;
        kr0 = ((const uint4*)(kbg + off))[0];
        kr1 = ((const uint4*)(kbg + off))[1];
        va  = *(const uint4*)(vbg + off);
        vb  = *(const uint4*)(vbg + off + 768);
    }
    __syncthreads();

    for (int T = 0; T < 64; T++) {
        const int b = T & 1;

        // store tile T+1 (regs) into the other buffer; prefetch T+2
        if (T < 63) {
            uint16_t* Kd = Khi[1 - b];
            uint16_t* Vd = Vthi[1 - b];
            *(uint4*)&Kd[klr * 40 + klc]     = kr0;
            *(uint4*)&Kd[klr * 40 + klc + 8] = kr1;
            const uint32_t aw[4] = {va.x, va.y, va.z, va.w};
            const uint32_t bw[4] = {vb.x, vb.y, vb.z, vb.w};
#pragma unroll
            for (int d = 0; d < 8; d++) {
                uint32_t x = prmt(aw[d >> 1], bw[d >> 1], (d & 1) ? 0x7632u : 0x5410u);
                *(uint32_t*)&Vd[(vc + d) * 72 + 2 * vj] = x;
            }
        }
        if (T < 62) {
            const size_t off = (size_t)(T + 2) * 64 * 768;
            kr0 = ((const uint4*)(kbg + off))[0];
            kr1 = ((const uint4*)(kbg + off))[1];
            va  = *(const uint4*)(vbg + off);
            vb  = *(const uint4*)(vbg + off + 768);
        }

        const uint32_t wA0 = mb[(size_t)rA * 128 + 2 * T];
        const uint32_t wA1 = mb[(size_t)rA * 128 + 2 * T + 1];
        const uint32_t wB0 = mb[(size_t)rB * 128 + 2 * T];
        const uint32_t wB1 = mb[(size_t)rB * 128 + 2 * T + 1];

        // ---- S = Q.K^T ----
        float c[8][4];
#pragma unroll
        for (int n = 0; n < 8; n++)
#pragma unroll
            for (int i = 0; i < 4; i++) c[n][i] = 0.0f;

#pragma unroll
        for (int p = 0; p < 4; p++) {
#pragma unroll
            for (int s = 0; s < 2; s++) {
                uint32_t bfr[4];
                ldsm4(bfr, kaddr + (uint32_t)(b * KBUF + (p * 16 * 40 + s * 16) * 2));
                mma_f16(c[2 * p],     qa[s], bfr[0], bfr[1]);
                mma_f16(c[2 * p + 1], qa[s], bfr[2], bfr[3]);
            }
        }

        // ---- mask + pack + f16x2 exp ----
        uint32_t pp[16];
#pragma unroll
        for (int n = 0; n < 8; n++) {
            const int sh = (8 * n + 2 * t) & 31;
            uint32_t bA = ((n < 4) ? wA0 : wA1) >> sh;
            uint32_t bB = ((n < 4) ? wB0 : wB1) >> sh;
            float s0 = (bA & 1u) ? c[n][0] : MNEG;
            float s1 = (bA & 2u) ? c[n][1] : MNEG;
            float s2 = (bB & 1u) ? c[n][2] : MNEG;
            float s3 = (bB & 2u) ? c[n][3] : MNEG;
            pp[2 * n]     = hex2(pkh(s0, s1));
            pp[2 * n + 1] = hex2(pkh(s2, s3));
        }

        // ---- out += P.V  (+ l via ones-column tile) ----
#pragma unroll
        for (int s = 0; s < 4; s++) {
            uint32_t ph[4] = {pp[4 * s], pp[4 * s + 1], pp[4 * s + 2], pp[4 * s + 3]};
#pragma unroll
            for (int p = 0; p < 2; p++) {
                uint32_t bfr[4];
                ldsm4(bfr, vaddr + (uint32_t)(b * VBUF + (p * 16 * 72 + s * 16) * 2));
                mma_f16(o[2 * p],     ph, bfr[0], bfr[1]);
                mma_f16(o[2 * p + 1], ph, bfr[2], bfr[3]);
            }
            uint32_t bl[2];
            ldsm2(bl, laddr + (uint32_t)(b * VBUF + s * 16 * 2));
            mma_f16(o4, ph, bl[0], bl[1]);
        }

        __syncthreads();
    }

    // ---- l lives in o4[0]/o4[2] of each row group's t=0 thread ----
    const float lAv = __shfl_sync(0xffffffffu, o4[0], lane & ~3);
    const float lBv = __shfl_sync(0xffffffffu, o4[2], lane & ~3);
    const float invA = 1.0f / lAv;
    const float invB = 1.0f / lBv;
    const int cb = h * 32 + 2 * t;
#pragma unroll
    for (int n = 0; n < 4; n++) {
        uint32_t hh, ll;
        splith(o[n][0] * invA, o[n][1] * invA, hh, ll);
        *(uint32_t*)&outh[(size_t)rA * 256 + cb + 8 * n] = hh;
        *(uint32_t*)&outl[(size_t)rA * 256 + cb + 8 * n] = ll;
        splith(o[n][2] * invB, o[n][3] * invB, hh, ll);
        *(uint32_t*)&outh[(size_t)rB * 256 + cb + 8 * n] = hh;
        *(uint32_t*)&outl[(size_t)rB * 256 + cb + 8 * n] = ll;
    }
}

// ---------------------------------------------------------------------------
extern "C" void kernel_launch(void* const* d_in, const int* in_sizes, int n_in,
                              void* d_out, int out_size)
{
    const float* x      = (const float*)d_in[0];
    const int*   adj    = (const int*)d_in[1];
    const float* w_qkv  = (const float*)d_in[2];
    const float* w_proj = (const float*)d_in[3];
    const float* b_proj = (const float*)d_in[4];
    float*       out    = (float*)d_out;

    void *pm, *pxh, *pxl, *pqh, *pql, *pph, *ppl, *pkv, *pah, *pal;
    cudaGetSymbolAddress(&pm, g_mask);
    cudaGetSymbolAddress(&pxh, g_xhi);  cudaGetSymbolAddress(&pxl, g_xlo);
    cudaGetSymbolAddress(&pqh, g_wqh);  cudaGetSymbolAddress(&pql, g_wql);
    cudaGetSymbolAddress(&pph, g_wph);  cudaGetSymbolAddress(&ppl, g_wpl);
    cudaGetSymbolAddress(&pkv, g_kvh);
    cudaGetSymbolAddress(&pah, g_ath);  cudaGetSymbolAddress(&pal, g_atl);

    uint32_t* msk = (uint32_t*)pm;
    uint16_t* xhi = (uint16_t*)pxh; uint16_t* xlo = (uint16_t*)pxl;
    uint16_t* wqh = (uint16_t*)pqh; uint16_t* wql = (uint16_t*)pql;
    uint16_t* wph = (uint16_t*)pph; uint16_t* wpl = (uint16_t*)ppl;
    uint16_t* kvh = (uint16_t*)pkv;
    uint16_t* ath = (uint16_t*)pah; uint16_t* atl = (uint16_t*)pal;

    // 0) packs
    pack_mask<<<(NTOK * (NTOK / 32)) / 256, 256>>>(adj, msk);
    pack_halves<<<(NTOK * CDIM / 4) / 256, 256>>>(x, xhi, xlo);
    pack_halves<<<(3 * CDIM * CDIM / 4) / 256, 256>>>(w_qkv, wqh, wql);
    pack_halves<<<(CDIM * CDIM / 4) / 256, 256>>>(w_proj, wph, wpl);

    // 1) QKV projection -> fp16 (q columns pre-scaled)
    {
        dim3 grid(768 / 64, NTOK / 128);
        gemm_tch<<<grid, 256>>>(xhi, xlo, wqh, wql, kvh, NTOK, 3 * CDIM, CDIM);
    }
    // 2) tensor-core masked flash attention -> fp16 hi/lo output
    {
        dim3 grid(NTOK / 64, HEADS);
        attn_tc<<<grid, 128>>>(kvh, msk, ath, atl);
    }
    // 3) output projection + bias (f32 out)
    {
        dim3 grid(CDIM / 64, NTOK / 128);
        gemm_tc<<<grid, 256>>>(ath, atl, wph, wpl, b_proj, out,
                               NTOK, CDIM, CDIM);
    }
}

// round 15
// speedup vs baseline: 1.0328x; 1.0328x over previous
#include <cuda_runtime.h>
#include <cuda_fp16.h>
#include <cstdint>

#define NTOK 4096
#define CDIM 256
#define HEADS 8
#define NEGBIG (-1.0e30f)
#define QSCALE (0.17677669529663687f * 1.4426950408889634f)

// scratch (allocation-free rule: device globals)
__device__ uint32_t g_mask[NTOK * (NTOK / 32)];    // packed adj bitmask, 2 MB
__device__ uint16_t g_xhi[NTOK * CDIM],  g_xlo[NTOK * CDIM];        // x split
__device__ uint16_t g_wqh[3 * CDIM * CDIM], g_wql[3 * CDIM * CDIM]; // w_qkv split
__device__ uint16_t g_wph[CDIM * CDIM],  g_wpl[CDIM * CDIM];        // w_proj split
__device__ uint16_t g_kvh[NTOK * 3 * CDIM];        // qkv fp16 (q pre-scaled)
__device__ uint16_t g_ath[NTOK * CDIM],  g_atl[NTOK * CDIM];        // attn out split

// ---------------------------------------------------------------------------
// helpers
// ---------------------------------------------------------------------------
__device__ __forceinline__ float ex2(float x) {
    float y;
    asm("ex2.approx.ftz.f32 %0, %1;" : "=f"(y) : "f"(x));
    return y;
}
__device__ __forceinline__ uint32_t pkh(float x, float y) {  // f16x2(lo=x,hi=y)
    uint32_t r;
    asm("cvt.rn.f16x2.f32 %0, %1, %2;" : "=r"(r) : "f"(y), "f"(x));
    return r;
}
__device__ __forceinline__ void splith(float x, float y, uint32_t& hi, uint32_t& lo) {
    uint32_t h = pkh(x, y);
    float xh, yh;
    asm("{ .reg .f16 a,b;\n  mov.b32 {a,b}, %2;\n  cvt.f32.f16 %0, a;\n  cvt.f32.f16 %1, b; }"
        : "=f"(xh), "=f"(yh) : "r"(h));
    hi = h;
    lo = pkh(x - xh, y - yh);
}
__device__ __forceinline__ uint32_t prmt(uint32_t a, uint32_t b, uint32_t sel) {
    uint32_t r;
    asm("prmt.b32 %0, %1, %2, %3;" : "=r"(r) : "r"(a), "r"(b), "r"(sel));
    return r;
}
__device__ __forceinline__ uint32_t smem_u32(const void* p) {
    uint32_t a;
    asm("{ .reg .u64 t; cvta.to.shared.u64 t, %1; cvt.u32.u64 %0, t; }" : "=r"(a) : "l"(p));
    return a;
}
// m16n8k16 fp16 MMA, f32 accumulate (A row-major, B col-major)
__device__ __forceinline__ void mma_f16(float* c, const uint32_t* a,
                                        uint32_t b0, uint32_t b1) {
    asm volatile(
        "mma.sync.aligned.m16n8k16.row.col.f32.f16.f16.f32 "
        "{%0,%1,%2,%3}, {%4,%5,%6,%7}, {%8,%9}, {%0,%1,%2,%3};"
        : "+f"(c[0]), "+f"(c[1]), "+f"(c[2]), "+f"(c[3])
        : "r"(a[0]), "r"(a[1]), "r"(a[2]), "r"(a[3]), "r"(b0), "r"(b1));
}
__device__ __forceinline__ void ldsm4(uint32_t* r, uint32_t a) {
    asm volatile("ldmatrix.sync.aligned.m8n8.x4.shared.b16 {%0,%1,%2,%3}, [%4];"
        : "=r"(r[0]), "=r"(r[1]), "=r"(r[2]), "=r"(r[3]) : "r"(a));
}

// ---------------------------------------------------------------------------
// pack adj into bitmask
// ---------------------------------------------------------------------------
__global__ __launch_bounds__(256) void pack_mask(
    const int* __restrict__ adj, uint32_t* __restrict__ mb)
{
    int w = blockIdx.x * blockDim.x + threadIdx.x;
    const int4* p = (const int4*)(adj + (size_t)w * 32);
    uint32_t bits = 0;
#pragma unroll
    for (int i = 0; i < 8; i++) {
        int4 a = p[i];
        bits |= (a.x > 0 ? 1u : 0u) << (4 * i + 0);
        bits |= (a.y > 0 ? 1u : 0u) << (4 * i + 1);
        bits |= (a.z > 0 ? 1u : 0u) << (4 * i + 2);
        bits |= (a.w > 0 ? 1u : 0u) << (4 * i + 3);
    }
    mb[w] = bits;
}

// ---------------------------------------------------------------------------
// pack f32 -> fp16 hi + fp16 lo residual (4 floats per thread)
// ---------------------------------------------------------------------------
__global__ __launch_bounds__(256) void pack_halves(
    const float* __restrict__ src, uint16_t* __restrict__ hi,
    uint16_t* __restrict__ lo)
{
    int i = blockIdx.x * blockDim.x + threadIdx.x;
    float4 f = ((const float4*)src)[i];
    uint32_t h01, l01, h23, l23;
    splith(f.x, f.y, h01, l01);
    splith(f.z, f.w, h23, l23);
    ((uint2*)hi)[i] = make_uint2(h01, h23);
    ((uint2*)lo)[i] = make_uint2(l01, l23);
}

// ---------------------------------------------------------------------------
// Split-fp16 tensor-core GEMM core (3 terms). Block tile 128x64, 256 threads,
// warp tile 32x32, BK=32.
// ---------------------------------------------------------------------------
#define GEMM_BODY                                                              \
    __shared__ uint16_t sA[2][128 * 40];                                       \
    __shared__ uint16_t sB[2][64 * 40];                                        \
    const int tid = threadIdx.x;                                               \
    const int w    = tid >> 5;                                                 \
    const int lane = tid & 31;                                                 \
    const int g    = lane >> 2;                                                \
    const int t    = lane & 3;                                                 \
    const int wm   = w >> 1;                                                   \
    const int wn   = w & 1;                                                    \
    const int m0 = blockIdx.y << 7;                                            \
    const int n0 = blockIdx.x << 6;                                            \
    const int ar = tid >> 1, ac = (tid & 1) * 16;                              \
    const int br = tid >> 2, bc = (tid & 3) * 8;                               \
    const uint16_t* Ah = Ahi + (size_t)(m0 + ar) * K + ac;                     \
    const uint16_t* Al = Alo + (size_t)(m0 + ar) * K + ac;                     \
    const uint16_t* Bh = Bhi + (size_t)(n0 + br) * K + bc;                     \
    const uint16_t* Bl = Blo + (size_t)(n0 + br) * K + bc;                     \
    float c[2][4][4];                                                          \
    _Pragma("unroll")                                                          \
    for (int i = 0; i < 2; i++)                                                \
        _Pragma("unroll")                                                      \
        for (int n = 0; n < 4; n++)                                            \
            _Pragma("unroll")                                                  \
            for (int j = 0; j < 4; j++) c[i][n][j] = 0.0f;                     \
    uint4 pah0 = ((const uint4*)Ah)[0], pah1 = ((const uint4*)Ah)[1];          \
    uint4 pal0 = ((const uint4*)Al)[0], pal1 = ((const uint4*)Al)[1];          \
    uint4 pbh  = ((const uint4*)Bh)[0];                                        \
    uint4 pbl  = ((const uint4*)Bl)[0];                                        \
    for (int k0 = 0; k0 < K; k0 += 32) {                                       \
        __syncthreads();                                                       \
        *(uint4*)&sA[0][ar * 40 + ac]     = pah0;                              \
        *(uint4*)&sA[0][ar * 40 + ac + 8] = pah1;                              \
        *(uint4*)&sA[1][ar * 40 + ac]     = pal0;                              \
        *(uint4*)&sA[1][ar * 40 + ac + 8] = pal1;                              \
        *(uint4*)&sB[0][br * 40 + bc]     = pbh;                               \
        *(uint4*)&sB[1][br * 40 + bc]     = pbl;                               \
        __syncthreads();                                                       \
        if (k0 + 32 < K) {                                                     \
            pah0 = ((const uint4*)(Ah + k0 + 32))[0];                          \
            pah1 = ((const uint4*)(Ah + k0 + 32))[1];                          \
            pal0 = ((const uint4*)(Al + k0 + 32))[0];                          \
            pal1 = ((const uint4*)(Al + k0 + 32))[1];                          \
            pbh  = ((const uint4*)(Bh + k0 + 32))[0];                          \
            pbl  = ((const uint4*)(Bl + k0 + 32))[0];                          \
        }                                                                      \
        _Pragma("unroll")                                                      \
        for (int s = 0; s < 2; s++) {                                          \
            uint32_t ah[2][4], al[2][4];                                       \
            _Pragma("unroll")                                                  \
            for (int i = 0; i < 2; i++) {                                      \
                const int r0 = (wm * 32 + i * 16 + g) * 40 + 16 * s + 2 * t;   \
                const int r1 = r0 + 8 * 40;                                    \
                ah[i][0] = *(const uint32_t*)&sA[0][r0];                       \
                ah[i][1] = *(const uint32_t*)&sA[0][r1];                       \
                ah[i][2] = *(const uint32_t*)&sA[0][r0 + 8];                   \
                ah[i][3] = *(const uint32_t*)&sA[0][r1 + 8];                   \
                al[i][0] = *(const uint32_t*)&sA[1][r0];                       \
                al[i][1] = *(const uint32_t*)&sA[1][r1];                       \
                al[i][2] = *(const uint32_t*)&sA[1][r0 + 8];                   \
                al[i][3] = *(const uint32_t*)&sA[1][r1 + 8];                   \
            }                                                                  \
            _Pragma("unroll")                                                  \
            for (int n = 0; n < 4; n++) {                                      \
                const int ro = (wn * 32 + n * 8 + g) * 40 + 16 * s + 2 * t;    \
                uint32_t bh0 = *(const uint32_t*)&sB[0][ro];                   \
                uint32_t bh1 = *(const uint32_t*)&sB[0][ro + 8];               \
                uint32_t bl0 = *(const uint32_t*)&sB[1][ro];                   \
                uint32_t bl1 = *(const uint32_t*)&sB[1][ro + 8];               \
                _Pragma("unroll")                                              \
                for (int i = 0; i < 2; i++) {                                  \
                    mma_f16(c[i][n], ah[i], bh0, bh1);                         \
                    mma_f16(c[i][n], ah[i], bl0, bl1);                         \
                    mma_f16(c[i][n], al[i], bh0, bh1);                         \
                }                                                              \
            }                                                                  \
        }                                                                      \
    }

__global__ __launch_bounds__(256) void gemm_tc(
    const uint16_t* __restrict__ Ahi, const uint16_t* __restrict__ Alo,
    const uint16_t* __restrict__ Bhi, const uint16_t* __restrict__ Blo,
    const float* __restrict__ bias, float* __restrict__ Y,
    int M, int Nn, int K)
{
    GEMM_BODY
#pragma unroll
    for (int n = 0; n < 4; n++) {
        const int col = n0 + wn * 32 + n * 8 + 2 * t;
        float b0 = 0.f, b1 = 0.f;
        if (bias) { b0 = bias[col]; b1 = bias[col + 1]; }
#pragma unroll
        for (int i = 0; i < 2; i++) {
            const int row0 = m0 + wm * 32 + i * 16 + g;
            float2 v0; v0.x = c[i][n][0] + b0; v0.y = c[i][n][1] + b1;
            float2 v1; v1.x = c[i][n][2] + b0; v1.y = c[i][n][3] + b1;
            *(float2*)(Y + (size_t)row0 * Nn + col) = v0;
            *(float2*)(Y + (size_t)(row0 + 8) * Nn + col) = v1;
        }
    }
}

// hi-only fp16 output; q columns (col < 256) scaled by QSCALE
__global__ __launch_bounds__(256) void gemm_tch(
    const uint16_t* __restrict__ Ahi, const uint16_t* __restrict__ Alo,
    const uint16_t* __restrict__ Bhi, const uint16_t* __restrict__ Blo,
    uint16_t* __restrict__ Yh, int M, int Nn, int K)
{
    GEMM_BODY
    const float sc = (n0 < 256) ? QSCALE : 1.0f;
#pragma unroll
    for (int n = 0; n < 4; n++) {
        const int col = n0 + wn * 32 + n * 8 + 2 * t;
#pragma unroll
        for (int i = 0; i < 2; i++) {
            const int row0 = m0 + wm * 32 + i * 16 + g;
            *(uint32_t*)&Yh[(size_t)row0 * Nn + col] =
                pkh(c[i][n][0] * sc, c[i][n][1] * sc);
            *(uint32_t*)&Yh[(size_t)(row0 + 8) * Nn + col] =
                pkh(c[i][n][2] * sc, c[i][n][3] * sc);
        }
    }
}

// ---------------------------------------------------------------------------
// Tensor-core flash attention, pure fp16, fixed-zero softmax reference.
// Block: 64 q-rows x 1 head, 128 threads, occupancy 4 (single wave).
// Chunk-pipelined S+exp: chunk p+1's S-MMAs issue BEFORE chunk p's
// mask/exp/pack so MUFU/FMA work overlaps the tensor-pipe drain (legal:
// fixed-zero reference => exp is per-element, no row max).
// Ping-pong K/V smem, ONE __syncthreads per tile. Mask-word LDGs hoisted
// above the S prologue (front-batched with the K/V prefetch for MLP).
// ---------------------------------------------------------------------------
#define KBUF (64 * 40 * 2)   // bytes per K buffer
#define VBUF (32 * 72 * 2)   // bytes per V buffer

__global__ __launch_bounds__(128, 4) void attn_tc(
    const uint16_t* __restrict__ qkv, const uint32_t* __restrict__ mb,
    uint16_t* __restrict__ outh, uint16_t* __restrict__ outl)
{
    __shared__ __align__(16) uint16_t Khi[2][64 * 40];
    __shared__ __align__(16) uint16_t Vthi[2][32 * 72];

    const int tid  = threadIdx.x;
    const int w    = tid >> 5;
    const int lane = tid & 31;
    const int g    = lane >> 2;
    const int t    = lane & 3;
    const int h    = blockIdx.y;
    const int q0   = blockIdx.x << 6;
    const int rA   = q0 + w * 16 + g;
    const int rB   = rA + 8;

    // ldmatrix per-lane addressing (quadrant layout)
    const int rowadd = ((lane >> 4) & 1) * 8 + (lane & 7);
    const int coladd = ((lane >> 3) & 1) * 8;
    const uint32_t kaddr = smem_u32(Khi)  + (uint32_t)(rowadd * 40 + coladd) * 2u;
    const uint32_t vaddr = smem_u32(Vthi) + (uint32_t)(rowadd * 72 + coladd) * 2u;

    // ---- Q fragments: direct packed loads (scale already folded) ----
    uint32_t qa[2][4];
#pragma unroll
    for (int s = 0; s < 2; s++) {
        const size_t bA = (size_t)rA * 768 + h * 32 + 16 * s + 2 * t;
        const size_t bB = (size_t)rB * 768 + h * 32 + 16 * s + 2 * t;
        qa[s][0] = *(const uint32_t*)&qkv[bA];
        qa[s][1] = *(const uint32_t*)&qkv[bB];
        qa[s][2] = *(const uint32_t*)&qkv[bA + 8];
        qa[s][3] = *(const uint32_t*)&qkv[bB + 8];
    }

    float lA = 0.0f, lB = 0.0f;
    float o[4][4];
#pragma unroll
    for (int n = 0; n < 4; n++)
#pragma unroll
        for (int i = 0; i < 4; i++) o[n][i] = 0.0f;

    // loaders
    const int klr = tid >> 1;
    const int klc = (tid & 1) * 16;
    const uint16_t* kbg = qkv + (size_t)klr * 768 + 256 + h * 32 + klc;
    const int vj = tid >> 2;
    const int vc = (tid & 3) * 8;
    const uint16_t* vbg = qkv + (size_t)(2 * vj) * 768 + 512 + h * 32 + vc;

    // per-row mask walkers (advance by 2 words per tile)
    const uint32_t* mbA = mb + (size_t)rA * 128;
    const uint32_t* mbB = mb + (size_t)rB * 128;

    uint4 kr0, kr1, va, vb;
    // tile 0 -> buf 0
    {
        kr0 = ((const uint4*)kbg)[0];
        kr1 = ((const uint4*)kbg)[1];
        va  = *(const uint4*)vbg;
        vb  = *(const uint4*)(vbg + 768);
        *(uint4*)&Khi[0][klr * 40 + klc]     = kr0;
        *(uint4*)&Khi[0][klr * 40 + klc + 8] = kr1;
        const uint32_t aw[4] = {va.x, va.y, va.z, va.w};
        const uint32_t bw[4] = {vb.x, vb.y, vb.z, vb.w};
#pragma unroll
        for (int d = 0; d < 8; d++) {
            uint32_t x = prmt(aw[d >> 1], bw[d >> 1], (d & 1) ? 0x7632u : 0x5410u);
            *(uint32_t*)&Vthi[0][(vc + d) * 72 + 2 * vj] = x;
        }
    }
    // tile 1 -> regs
    {
        const size_t off = (size_t)64 * 768;
        kr0 = ((const uint4*)(kbg + off))[0];
        kr1 = ((const uint4*)(kbg + off))[1];
        va  = *(const uint4*)(vbg + off);
        vb  = *(const uint4*)(vbg + off + 768);
    }
    __syncthreads();

    for (int T = 0; T < 64; T++) {
        const int b = T & 1;

        // mask words first (front-batched with the prefetch LDGs below)
        const uint32_t wA0 = mbA[2 * T];
        const uint32_t wA1 = mbA[2 * T + 1];
        const uint32_t wB0 = mbB[2 * T];
        const uint32_t wB1 = mbB[2 * T + 1];

        // store tile T+1 (regs) into the other buffer; prefetch T+2
        if (T < 63) {
            uint16_t* Kd = Khi[1 - b];
            uint16_t* Vd = Vthi[1 - b];
            *(uint4*)&Kd[klr * 40 + klc]     = kr0;
            *(uint4*)&Kd[klr * 40 + klc + 8] = kr1;
            const uint32_t aw[4] = {va.x, va.y, va.z, va.w};
            const uint32_t bw[4] = {vb.x, vb.y, vb.z, vb.w};
#pragma unroll
            for (int d = 0; d < 8; d++) {
                uint32_t x = prmt(aw[d >> 1], bw[d >> 1], (d & 1) ? 0x7632u : 0x5410u);
                *(uint32_t*)&Vd[(vc + d) * 72 + 2 * vj] = x;
            }
        }
        if (T < 62) {
            const size_t off = (size_t)(T + 2) * 64 * 768;
            kr0 = ((const uint4*)(kbg + off))[0];
            kr1 = ((const uint4*)(kbg + off))[1];
            va  = *(const uint4*)(vbg + off);
            vb  = *(const uint4*)(vbg + off + 768);
        }

        // ---- S = Q.K^T, chunk-pipelined with mask/exp/pack ----
        // chunk p covers n-tiles {2p, 2p+1}; cc[p&1] holds its 8 accumulators
        float cc[2][8];
        uint32_t pp[16];

        // prologue: chunk 0 MMAs
#pragma unroll
        for (int i = 0; i < 8; i++) cc[0][i] = 0.0f;
#pragma unroll
        for (int s = 0; s < 2; s++) {
            uint32_t bfr[4];
            ldsm4(bfr, kaddr + (uint32_t)(b * KBUF + s * 16 * 2));
            mma_f16(&cc[0][0], qa[s], bfr[0], bfr[1]);
            mma_f16(&cc[0][4], qa[s], bfr[2], bfr[3]);
        }

#pragma unroll
        for (int p = 0; p < 4; p++) {
            // issue chunk p+1 MMAs first (independent of chunk p's exp)
            if (p < 3) {
                float* cn = cc[(p + 1) & 1];
#pragma unroll
                for (int i = 0; i < 8; i++) cn[i] = 0.0f;
#pragma unroll
                for (int s = 0; s < 2; s++) {
                    uint32_t bfr[4];
                    ldsm4(bfr, kaddr + (uint32_t)(b * KBUF +
                          ((p + 1) * 16 * 40 + s * 16) * 2));
                    mma_f16(&cn[0], qa[s], bfr[0], bfr[1]);
                    mma_f16(&cn[4], qa[s], bfr[2], bfr[3]);
                }
            }
            // mask + exp + pack chunk p (overlaps the MMAs above)
            const float* cp = cc[p & 1];
#pragma unroll
            for (int j = 0; j < 2; j++) {
                const int n = 2 * p + j;
                const int sh = (8 * n + 2 * t) & 31;
                uint32_t bA = ((n < 4) ? wA0 : wA1) >> sh;
                uint32_t bB = ((n < 4) ? wB0 : wB1) >> sh;
                float p0 = ex2((bA & 1u) ? cp[4 * j + 0] : NEGBIG);
                float p1 = ex2((bA & 2u) ? cp[4 * j + 1] : NEGBIG);
                float p2 = ex2((bB & 1u) ? cp[4 * j + 2] : NEGBIG);
                float p3 = ex2((bB & 2u) ? cp[4 * j + 3] : NEGBIG);
                lA += p0 + p1;
                lB += p2 + p3;
                pp[2 * n]     = pkh(p0, p1);
                pp[2 * n + 1] = pkh(p2, p3);
            }
        }

        // ---- out += P.V ----
#pragma unroll
        for (int s = 0; s < 4; s++) {
            uint32_t ph[4] = {pp[4 * s], pp[4 * s + 1], pp[4 * s + 2], pp[4 * s + 3]};
#pragma unroll
            for (int p = 0; p < 2; p++) {
                uint32_t bfr[4];
                ldsm4(bfr, vaddr + (uint32_t)(b * VBUF + (p * 16 * 72 + s * 16) * 2));
                mma_f16(o[2 * p],     ph, bfr[0], bfr[1]);
                mma_f16(o[2 * p + 1], ph, bfr[2], bfr[3]);
            }
        }

        __syncthreads();
    }

    // ---- reduce l across the 4 t-threads of each row, normalize, store ----
    lA += __shfl_xor_sync(0xffffffffu, lA, 1);
    lA += __shfl_xor_sync(0xffffffffu, lA, 2);
    lB += __shfl_xor_sync(0xffffffffu, lB, 1);
    lB += __shfl_xor_sync(0xffffffffu, lB, 2);
    const float invA = 1.0f / lA;
    const float invB = 1.0f / lB;
    const int cb = h * 32 + 2 * t;
#pragma unroll
    for (int n = 0; n < 4; n++) {
        uint32_t hh, ll;
        splith(o[n][0] * invA, o[n][1] * invA, hh, ll);
        *(uint32_t*)&outh[(size_t)rA * 256 + cb + 8 * n] = hh;
        *(uint32_t*)&outl[(size_t)rA * 256 + cb + 8 * n] = ll;
        splith(o[n][2] * invB, o[n][3] * invB, hh, ll);
        *(uint32_t*)&outh[(size_t)rB * 256 + cb + 8 * n] = hh;
        *(uint32_t*)&outl[(size_t)rB * 256 + cb + 8 * n] = ll;
    }
}

// ---------------------------------------------------------------------------
extern "C" void kernel_launch(void* const* d_in, const int* in_sizes, int n_in,
                              void* d_out, int out_size)
{
    const float* x      = (const float*)d_in[0];
    const int*   adj    = (const int*)d_in[1];
    const float* w_qkv  = (const float*)d_in[2];
    const float* w_proj = (const float*)d_in[3];
    const float* b_proj = (const float*)d_in[4];
    float*       out    = (float*)d_out;

    void *pm, *pxh, *pxl, *pqh, *pql, *pph, *ppl, *pkv, *pah, *pal;
    cudaGetSymbolAddress(&pm, g_mask);
    cudaGetSymbolAddress(&pxh, g_xhi);  cudaGetSymbolAddress(&pxl, g_xlo);
    cudaGetSymbolAddress(&pqh, g_wqh);  cudaGetSymbolAddress(&pql, g_wql);
    cudaGetSymbolAddress(&pph, g_wph);  cudaGetSymbolAddress(&ppl, g_wpl);
    cudaGetSymbolAddress(&pkv, g_kvh);
    cudaGetSymbolAddress(&pah, g_ath);  cudaGetSymbolAddress(&pal, g_atl);

    uint32_t* msk = (uint32_t*)pm;
    uint16_t* xhi = (uint16_t*)pxh; uint16_t* xlo = (uint16_t*)pxl;
    uint16_t* wqh = (uint16_t*)pqh; uint16_t* wql = (uint16_t*)pql;
    uint16_t* wph = (uint16_t*)pph; uint16_t* wpl = (uint16_t*)ppl;
    uint16_t* kvh = (uint16_t*)pkv;
    uint16_t* ath = (uint16_t*)pah; uint16_t* atl = (uint16_t*)pal;

    // 0) packs
    pack_mask<<<(NTOK * (NTOK / 32)) / 256, 256>>>(adj, msk);
    pack_halves<<<(NTOK * CDIM / 4) / 256, 256>>>(x, xhi, xlo);
    pack_halves<<<(3 * CDIM * CDIM / 4) / 256, 256>>>(w_qkv, wqh, wql);
    pack_halves<<<(CDIM * CDIM / 4) / 256, 256>>>(w_proj, wph, wpl);

    // 1) QKV projection -> fp16 (q columns pre-scaled)
    {
        dim3 grid(768 / 64, NTOK / 128);
        gemm_tch<<<grid, 256>>>(xhi, xlo, wqh, wql, kvh, NTOK, 3 * CDIM, CDIM);
    }
    // 2) tensor-core masked flash attention -> fp16 hi/lo output
    {
        dim3 grid(NTOK / 64, HEADS);
        attn_tc<<<grid, 128>>>(kvh, msk, ath, atl);
    }
    // 3) output projection + bias (f32 out)
    {
        dim3 grid(CDIM / 64, NTOK / 128);
        gemm_tc<<<grid, 256>>>(ath, atl, wph, wpl, b_proj, out,
                               NTOK, CDIM, CDIM);
    }
}

// round 16
// speedup vs baseline: 1.1627x; 1.1258x over previous
#include <cuda_runtime.h>
#include <cuda_fp16.h>
#include <cstdint>

#define NTOK 4096
#define CDIM 256
#define HEADS 8
#define NEGBIG (-1.0e30f)
#define QSCALE (0.17677669529663687f * 1.4426950408889634f)

// scratch (allocation-free rule: device globals)
__device__ uint32_t g_mask[NTOK * (NTOK / 32)];    // packed adj bitmask, 2 MB
__device__ uint16_t g_xhi[NTOK * CDIM],  g_xlo[NTOK * CDIM];        // x split
__device__ uint16_t g_wqh[3 * CDIM * CDIM], g_wql[3 * CDIM * CDIM]; // w_qkv split
__device__ uint16_t g_wph[CDIM * CDIM],  g_wpl[CDIM * CDIM];        // w_proj split
__device__ uint16_t g_kvh[NTOK * 3 * CDIM];        // qkv fp16 (q pre-scaled)
__device__ uint16_t g_ath[NTOK * CDIM],  g_atl[NTOK * CDIM];        // attn out split

// ---------------------------------------------------------------------------
// helpers
// ---------------------------------------------------------------------------
__device__ __forceinline__ float ex2(float x) {
    float y;
    asm("ex2.approx.ftz.f32 %0, %1;" : "=f"(y) : "f"(x));
    return y;
}
__device__ __forceinline__ uint32_t pkh(float x, float y) {  // f16x2(lo=x,hi=y)
    uint32_t r;
    asm("cvt.rn.f16x2.f32 %0, %1, %2;" : "=r"(r) : "f"(y), "f"(x));
    return r;
}
__device__ __forceinline__ void splith(float x, float y, uint32_t& hi, uint32_t& lo) {
    uint32_t h = pkh(x, y);
    float xh, yh;
    asm("{ .reg .f16 a,b;\n  mov.b32 {a,b}, %2;\n  cvt.f32.f16 %0, a;\n  cvt.f32.f16 %1, b; }"
        : "=f"(xh), "=f"(yh) : "r"(h));
    hi = h;
    lo = pkh(x - xh, y - yh);
}
__device__ __forceinline__ uint32_t prmt(uint32_t a, uint32_t b, uint32_t sel) {
    uint32_t r;
    asm("prmt.b32 %0, %1, %2, %3;" : "=r"(r) : "r"(a), "r"(b), "r"(sel));
    return r;
}
__device__ __forceinline__ uint32_t smem_u32(const void* p) {
    uint32_t a;
    asm("{ .reg .u64 t; cvta.to.shared.u64 t, %1; cvt.u32.u64 %0, t; }" : "=r"(a) : "l"(p));
    return a;
}
// m16n8k16 fp16 MMA, f32 accumulate (A row-major, B col-major)
__device__ __forceinline__ void mma_f16(float* c, const uint32_t* a,
                                        uint32_t b0, uint32_t b1) {
    asm volatile(
        "mma.sync.aligned.m16n8k16.row.col.f32.f16.f16.f32 "
        "{%0,%1,%2,%3}, {%4,%5,%6,%7}, {%8,%9}, {%0,%1,%2,%3};"
        : "+f"(c[0]), "+f"(c[1]), "+f"(c[2]), "+f"(c[3])
        : "r"(a[0]), "r"(a[1]), "r"(a[2]), "r"(a[3]), "r"(b0), "r"(b1));
}
__device__ __forceinline__ void ldsm4(uint32_t* r, uint32_t a) {
    asm volatile("ldmatrix.sync.aligned.m8n8.x4.shared.b16 {%0,%1,%2,%3}, [%4];"
        : "=r"(r[0]), "=r"(r[1]), "=r"(r[2]), "=r"(r[3]) : "r"(a));
}

// ---------------------------------------------------------------------------
// pack adj into bitmask
// ---------------------------------------------------------------------------
__global__ __launch_bounds__(256) void pack_mask(
    const int* __restrict__ adj, uint32_t* __restrict__ mb)
{
    int w = blockIdx.x * blockDim.x + threadIdx.x;
    const int4* p = (const int4*)(adj + (size_t)w * 32);
    uint32_t bits = 0;
#pragma unroll
    for (int i = 0; i < 8; i++) {
        int4 a = p[i];
        bits |= (a.x > 0 ? 1u : 0u) << (4 * i + 0);
        bits |= (a.y > 0 ? 1u : 0u) << (4 * i + 1);
        bits |= (a.z > 0 ? 1u : 0u) << (4 * i + 2);
        bits |= (a.w > 0 ? 1u : 0u) << (4 * i + 3);
    }
    mb[w] = bits;
}

// ---------------------------------------------------------------------------
// pack ALL f32 operands -> fp16 hi/lo in ONE launch (x | w_qkv | w_proj)
// ---------------------------------------------------------------------------
#define XG  (NTOK * CDIM / 4)          // 262144 groups of 4
#define WQG (3 * CDIM * CDIM / 4)      // 49152
#define WPG (CDIM * CDIM / 4)          // 16384
#define ALLG (XG + WQG + WPG)          // 327680 -> 1280 blocks x 256

__global__ __launch_bounds__(256) void pack_all(
    const float* __restrict__ x, const float* __restrict__ wq,
    const float* __restrict__ wp,
    uint16_t* __restrict__ xhi, uint16_t* __restrict__ xlo,
    uint16_t* __restrict__ wqh, uint16_t* __restrict__ wql,
    uint16_t* __restrict__ wph, uint16_t* __restrict__ wpl)
{
    int i = blockIdx.x * blockDim.x + threadIdx.x;
    const float* src;
    uint16_t *hi, *lo;
    int j;
    if (i < XG)            { src = x;  hi = xhi; lo = xlo; j = i; }
    else if (i < XG + WQG) { src = wq; hi = wqh; lo = wql; j = i - XG; }
    else                   { src = wp; hi = wph; lo = wpl; j = i - XG - WQG; }
    float4 f = ((const float4*)src)[j];
    uint32_t h01, l01, h23, l23;
    splith(f.x, f.y, h01, l01);
    splith(f.z, f.w, h23, l23);
    ((uint2*)hi)[j] = make_uint2(h01, h23);
    ((uint2*)lo)[j] = make_uint2(l01, l23);
}

// ---------------------------------------------------------------------------
// Split-fp16 tensor-core GEMM core. Block tile 128x64, 256 threads,
// warp tile 32x32, BK=32. DO_ABL: include the Ah.Bl cross-term (3-term) or
// not (2-term; B_lo path skipped entirely).
// ---------------------------------------------------------------------------
#define GEMM_BODY(DO_ABL)                                                      \
    __shared__ uint16_t sA[2][128 * 40];                                       \
    __shared__ uint16_t sB[2][64 * 40];                                        \
    const int tid = threadIdx.x;                                               \
    const int w    = tid >> 5;                                                 \
    const int lane = tid & 31;                                                 \
    const int g    = lane >> 2;                                                \
    const int t    = lane & 3;                                                 \
    const int wm   = w >> 1;                                                   \
    const int wn   = w & 1;                                                    \
    const int m0 = blockIdx.y << 7;                                            \
    const int n0 = blockIdx.x << 6;                                            \
    const int ar = tid >> 1, ac = (tid & 1) * 16;                              \
    const int br = tid >> 2, bc = (tid & 3) * 8;                               \
    const uint16_t* Ah = Ahi + (size_t)(m0 + ar) * K + ac;                     \
    const uint16_t* Al = Alo + (size_t)(m0 + ar) * K + ac;                     \
    const uint16_t* Bh = Bhi + (size_t)(n0 + br) * K + bc;                     \
    const uint16_t* Bl = Blo + (size_t)(n0 + br) * K + bc;                     \
    float c[2][4][4];                                                          \
    _Pragma("unroll")                                                          \
    for (int i = 0; i < 2; i++)                                                \
        _Pragma("unroll")                                                      \
        for (int n = 0; n < 4; n++)                                            \
            _Pragma("unroll")                                                  \
            for (int j = 0; j < 4; j++) c[i][n][j] = 0.0f;                     \
    uint4 pah0 = ((const uint4*)Ah)[0], pah1 = ((const uint4*)Ah)[1];          \
    uint4 pal0 = ((const uint4*)Al)[0], pal1 = ((const uint4*)Al)[1];          \
    uint4 pbh  = ((const uint4*)Bh)[0];                                        \
    uint4 pbl  = make_uint4(0, 0, 0, 0);                                       \
    if (DO_ABL) pbl = ((const uint4*)Bl)[0];                                   \
    for (int k0 = 0; k0 < K; k0 += 32) {                                       \
        __syncthreads();                                                       \
        *(uint4*)&sA[0][ar * 40 + ac]     = pah0;                              \
        *(uint4*)&sA[0][ar * 40 + ac + 8] = pah1;                              \
        *(uint4*)&sA[1][ar * 40 + ac]     = pal0;                              \
        *(uint4*)&sA[1][ar * 40 + ac + 8] = pal1;                              \
        *(uint4*)&sB[0][br * 40 + bc]     = pbh;                               \
        if (DO_ABL) *(uint4*)&sB[1][br * 40 + bc] = pbl;                       \
        __syncthreads();                                                       \
        if (k0 + 32 < K) {                                                     \
            pah0 = ((const uint4*)(Ah + k0 + 32))[0];                          \
            pah1 = ((const uint4*)(Ah + k0 + 32))[1];                          \
            pal0 = ((const uint4*)(Al + k0 + 32))[0];                          \
            pal1 = ((const uint4*)(Al + k0 + 32))[1];                          \
            pbh  = ((const uint4*)(Bh + k0 + 32))[0];                          \
            if (DO_ABL) pbl = ((const uint4*)(Bl + k0 + 32))[0];               \
        }                                                                      \
        _Pragma("unroll")                                                      \
        for (int s = 0; s < 2; s++) {                                          \
            uint32_t ah[2][4], al[2][4];                                       \
            _Pragma("unroll")                                                  \
            for (int i = 0; i < 2; i++) {                                      \
                const int r0 = (wm * 32 + i * 16 + g) * 40 + 16 * s + 2 * t;   \
                const int r1 = r0 + 8 * 40;                                    \
                ah[i][0] = *(const uint32_t*)&sA[0][r0];                       \
                ah[i][1] = *(const uint32_t*)&sA[0][r1];                       \
                ah[i][2] = *(const uint32_t*)&sA[0][r0 + 8];                   \
                ah[i][3] = *(const uint32_t*)&sA[0][r1 + 8];                   \
                al[i][0] = *(const uint32_t*)&sA[1][r0];                       \
                al[i][1] = *(const uint32_t*)&sA[1][r1];                       \
                al[i][2] = *(const uint32_t*)&sA[1][r0 + 8];                   \
                al[i][3] = *(const uint32_t*)&sA[1][r1 + 8];                   \
            }                                                                  \
            _Pragma("unroll")                                                  \
            for (int n = 0; n < 4; n++) {                                      \
                const int ro = (wn * 32 + n * 8 + g) * 40 + 16 * s + 2 * t;    \
                uint32_t bh0 = *(const uint32_t*)&sB[0][ro];                   \
                uint32_t bh1 = *(const uint32_t*)&sB[0][ro + 8];               \
                _Pragma("unroll")                                              \
                for (int i = 0; i < 2; i++) {                                  \
                    mma_f16(c[i][n], ah[i], bh0, bh1);                         \
                    mma_f16(c[i][n], al[i], bh0, bh1);                         \
                }                                                              \
                if (DO_ABL) {                                                  \
                    uint32_t bl0 = *(const uint32_t*)&sB[1][ro];               \
                    uint32_t bl1 = *(const uint32_t*)&sB[1][ro + 8];           \
                    _Pragma("unroll")                                          \
                    for (int i = 0; i < 2; i++)                                \
                        mma_f16(c[i][n], ah[i], bl0, bl1);                     \
                }                                                              \
            }                                                                  \
        }                                                                      \
    }

// 3-term, f32 output + bias (final projection)
__global__ __launch_bounds__(256) void gemm_tc(
    const uint16_t* __restrict__ Ahi, const uint16_t* __restrict__ Alo,
    const uint16_t* __restrict__ Bhi, const uint16_t* __restrict__ Blo,
    const float* __restrict__ bias, float* __restrict__ Y,
    int M, int Nn, int K)
{
    GEMM_BODY(1)
#pragma unroll
    for (int n = 0; n < 4; n++) {
        const int col = n0 + wn * 32 + n * 8 + 2 * t;
        float b0 = 0.f, b1 = 0.f;
        if (bias) { b0 = bias[col]; b1 = bias[col + 1]; }
#pragma unroll
        for (int i = 0; i < 2; i++) {
            const int row0 = m0 + wm * 32 + i * 16 + g;
            float2 v0; v0.x = c[i][n][0] + b0; v0.y = c[i][n][1] + b1;
            float2 v1; v1.x = c[i][n][2] + b0; v1.y = c[i][n][3] + b1;
            *(float2*)(Y + (size_t)row0 * Nn + col) = v0;
            *(float2*)(Y + (size_t)(row0 + 8) * Nn + col) = v1;
        }
    }
}

// 2-term (output rounded to fp16 anyway), q columns scaled by QSCALE
__global__ __launch_bounds__(256) void gemm_tch(
    const uint16_t* __restrict__ Ahi, const uint16_t* __restrict__ Alo,
    const uint16_t* __restrict__ Bhi, const uint16_t* __restrict__ Blo,
    uint16_t* __restrict__ Yh, int M, int Nn, int K)
{
    GEMM_BODY(0)
    const float sc = (n0 < 256) ? QSCALE : 1.0f;
#pragma unroll
    for (int n = 0; n < 4; n++) {
        const int col = n0 + wn * 32 + n * 8 + 2 * t;
#pragma unroll
        for (int i = 0; i < 2; i++) {
            const int row0 = m0 + wm * 32 + i * 16 + g;
            *(uint32_t*)&Yh[(size_t)row0 * Nn + col] =
                pkh(c[i][n][0] * sc, c[i][n][1] * sc);
            *(uint32_t*)&Yh[(size_t)(row0 + 8) * Nn + col] =
                pkh(c[i][n][2] * sc, c[i][n][3] * sc);
        }
    }
}

// ---------------------------------------------------------------------------
// Tensor-core flash attention, pure fp16, fixed-zero softmax reference.
// R16: block = 128 q-rows x 1 head, 256 threads (8 warps), occupancy 2,
// grid 256 (single wave). K/V tile fill amortized over 8 warps: warps 0-3
// load K, warps 4-7 load+transpose V (warp-uniform split). Chunk-pipelined
// S+exp, ping-pong smem, one __syncthreads per tile.
// ---------------------------------------------------------------------------
#define KBUF (64 * 40 * 2)   // bytes per K buffer
#define VBUF (32 * 72 * 2)   // bytes per V buffer

__global__ __launch_bounds__(256, 2) void attn_tc(
    const uint16_t* __restrict__ qkv, const uint32_t* __restrict__ mb,
    uint16_t* __restrict__ outh, uint16_t* __restrict__ outl)
{
    __shared__ __align__(16) uint16_t Khi[2][64 * 40];
    __shared__ __align__(16) uint16_t Vthi[2][32 * 72];

    const int tid  = threadIdx.x;
    const int w    = tid >> 5;
    const int lane = tid & 31;
    const int g    = lane >> 2;
    const int t    = lane & 3;
    const int h    = blockIdx.y;
    const int q0   = blockIdx.x << 7;
    const int rA   = q0 + w * 16 + g;
    const int rB   = rA + 8;

    // ldmatrix per-lane addressing (quadrant layout)
    const int rowadd = ((lane >> 4) & 1) * 8 + (lane & 7);
    const int coladd = ((lane >> 3) & 1) * 8;
    const uint32_t kaddr = smem_u32(Khi)  + (uint32_t)(rowadd * 40 + coladd) * 2u;
    const uint32_t vaddr = smem_u32(Vthi) + (uint32_t)(rowadd * 72 + coladd) * 2u;

    // ---- Q fragments ----
    uint32_t qa[2][4];
#pragma unroll
    for (int s = 0; s < 2; s++) {
        const size_t bA = (size_t)rA * 768 + h * 32 + 16 * s + 2 * t;
        const size_t bB = (size_t)rB * 768 + h * 32 + 16 * s + 2 * t;
        qa[s][0] = *(const uint32_t*)&qkv[bA];
        qa[s][1] = *(const uint32_t*)&qkv[bB];
        qa[s][2] = *(const uint32_t*)&qkv[bA + 8];
        qa[s][3] = *(const uint32_t*)&qkv[bB + 8];
    }

    float lA = 0.0f, lB = 0.0f;
    float o[4][4];
#pragma unroll
    for (int n = 0; n < 4; n++)
#pragma unroll
        for (int i = 0; i < 4; i++) o[n][i] = 0.0f;

    // loader split: warps 0-3 -> K, warps 4-7 -> V
    const int isv = (tid >= 128);
    const int lt  = tid & 127;
    const int klr = lt >> 1, klc = (lt & 1) * 16;
    const int vj  = lt >> 2, vc = (lt & 3) * 8;
    const uint16_t* kbg = qkv + (size_t)klr * 768 + 256 + h * 32 + klc;
    const uint16_t* vbg = qkv + (size_t)(2 * vj) * 768 + 512 + h * 32 + vc;

    // per-row mask walkers
    const uint32_t* mbA = mb + (size_t)rA * 128;
    const uint32_t* mbB = mb + (size_t)rB * 128;

    uint4 kr0, kr1, va, vb;
    // tile 0 -> buf 0
    if (!isv) {
        kr0 = ((const uint4*)kbg)[0];
        kr1 = ((const uint4*)kbg)[1];
        *(uint4*)&Khi[0][klr * 40 + klc]     = kr0;
        *(uint4*)&Khi[0][klr * 40 + klc + 8] = kr1;
    } else {
        va  = *(const uint4*)vbg;
        vb  = *(const uint4*)(vbg + 768);
        const uint32_t aw[4] = {va.x, va.y, va.z, va.w};
        const uint32_t bw[4] = {vb.x, vb.y, vb.z, vb.w};
#pragma unroll
        for (int d = 0; d < 8; d++) {
            uint32_t x = prmt(aw[d >> 1], bw[d >> 1], (d & 1) ? 0x7632u : 0x5410u);
            *(uint32_t*)&Vthi[0][(vc + d) * 72 + 2 * vj] = x;
        }
    }
    // tile 1 -> regs
    {
        const size_t off = (size_t)64 * 768;
        if (!isv) {
            kr0 = ((const uint4*)(kbg + off))[0];
            kr1 = ((const uint4*)(kbg + off))[1];
        } else {
            va  = *(const uint4*)(vbg + off);
            vb  = *(const uint4*)(vbg + off + 768);
        }
    }
    __syncthreads();

    for (int T = 0; T < 64; T++) {
        const int b = T & 1;

        // mask words (front-batched with the prefetch LDGs below)
        const uint32_t wA0 = mbA[2 * T];
        const uint32_t wA1 = mbA[2 * T + 1];
        const uint32_t wB0 = mbB[2 * T];
        const uint32_t wB1 = mbB[2 * T + 1];

        // store tile T+1 into the other buffer; prefetch T+2
        if (T < 63) {
            if (!isv) {
                uint16_t* Kd = Khi[1 - b];
                *(uint4*)&Kd[klr * 40 + klc]     = kr0;
                *(uint4*)&Kd[klr * 40 + klc + 8] = kr1;
            } else {
                uint16_t* Vd = Vthi[1 - b];
                const uint32_t aw[4] = {va.x, va.y, va.z, va.w};
                const uint32_t bw[4] = {vb.x, vb.y, vb.z, vb.w};
#pragma unroll
                for (int d = 0; d < 8; d++) {
                    uint32_t x = prmt(aw[d >> 1], bw[d >> 1],
                                      (d & 1) ? 0x7632u : 0x5410u);
                    *(uint32_t*)&Vd[(vc + d) * 72 + 2 * vj] = x;
                }
            }
        }
        if (T < 62) {
            const size_t off = (size_t)(T + 2) * 64 * 768;
            if (!isv) {
                kr0 = ((const uint4*)(kbg + off))[0];
                kr1 = ((const uint4*)(kbg + off))[1];
            } else {
                va  = *(const uint4*)(vbg + off);
                vb  = *(const uint4*)(vbg + off + 768);
            }
        }

        // ---- S = Q.K^T, chunk-pipelined with mask/exp/pack ----
        float cc[2][8];
        uint32_t pp[16];

#pragma unroll
        for (int i = 0; i < 8; i++) cc[0][i] = 0.0f;
#pragma unroll
        for (int s = 0; s < 2; s++) {
            uint32_t bfr[4];
            ldsm4(bfr, kaddr + (uint32_t)(b * KBUF + s * 16 * 2));
            mma_f16(&cc[0][0], qa[s], bfr[0], bfr[1]);
            mma_f16(&cc[0][4], qa[s], bfr[2], bfr[3]);
        }

#pragma unroll
        for (int p = 0; p < 4; p++) {
            if (p < 3) {
                float* cn = cc[(p + 1) & 1];
#pragma unroll
                for (int i = 0; i < 8; i++) cn[i] = 0.0f;
#pragma unroll
                for (int s = 0; s < 2; s++) {
                    uint32_t bfr[4];
                    ldsm4(bfr, kaddr + (uint32_t)(b * KBUF +
                          ((p + 1) * 16 * 40 + s * 16) * 2));
                    mma_f16(&cn[0], qa[s], bfr[0], bfr[1]);
                    mma_f16(&cn[4], qa[s], bfr[2], bfr[3]);
                }
            }
            const float* cp = cc[p & 1];
#pragma unroll
            for (int j = 0; j < 2; j++) {
                const int n = 2 * p + j;
                const int sh = (8 * n + 2 * t) & 31;
                uint32_t bA = ((n < 4) ? wA0 : wA1) >> sh;
                uint32_t bB = ((n < 4) ? wB0 : wB1) >> sh;
                float p0 = ex2((bA & 1u) ? cp[4 * j + 0] : NEGBIG);
                float p1 = ex2((bA & 2u) ? cp[4 * j + 1] : NEGBIG);
                float p2 = ex2((bB & 1u) ? cp[4 * j + 2] : NEGBIG);
                float p3 = ex2((bB & 2u) ? cp[4 * j + 3] : NEGBIG);
                lA += p0 + p1;
                lB += p2 + p3;
                pp[2 * n]     = pkh(p0, p1);
                pp[2 * n + 1] = pkh(p2, p3);
            }
        }

        // ---- out += P.V ----
#pragma unroll
        for (int s = 0; s < 4; s++) {
            uint32_t ph[4] = {pp[4 * s], pp[4 * s + 1], pp[4 * s + 2], pp[4 * s + 3]};
#pragma unroll
            for (int p = 0; p < 2; p++) {
                uint32_t bfr[4];
                ldsm4(bfr, vaddr + (uint32_t)(b * VBUF + (p * 16 * 72 + s * 16) * 2));
                mma_f16(o[2 * p],     ph, bfr[0], bfr[1]);
                mma_f16(o[2 * p + 1], ph, bfr[2], bfr[3]);
            }
        }

        __syncthreads();
    }

    // ---- reduce l, normalize, store ----
    lA += __shfl_xor_sync(0xffffffffu, lA, 1);
    lA += __shfl_xor_sync(0xffffffffu, lA, 2);
    lB += __shfl_xor_sync(0xffffffffu, lB, 1);
    lB += __shfl_xor_sync(0xffffffffu, lB, 2);
    const float invA = 1.0f / lA;
    const float invB = 1.0f / lB;
    const int cb = h * 32 + 2 * t;
#pragma unroll
    for (int n = 0; n < 4; n++) {
        uint32_t hh, ll;
        splith(o[n][0] * invA, o[n][1] * invA, hh, ll);
        *(uint32_t*)&outh[(size_t)rA * 256 + cb + 8 * n] = hh;
        *(uint32_t*)&outl[(size_t)rA * 256 + cb + 8 * n] = ll;
        splith(o[n][2] * invB, o[n][3] * invB, hh, ll);
        *(uint32_t*)&outh[(size_t)rB * 256 + cb + 8 * n] = hh;
        *(uint32_t*)&outl[(size_t)rB * 256 + cb + 8 * n] = ll;
    }
}

// ---------------------------------------------------------------------------
extern "C" void kernel_launch(void* const* d_in, const int* in_sizes, int n_in,
                              void* d_out, int out_size)
{
    const float* x      = (const float*)d_in[0];
    const int*   adj    = (const int*)d_in[1];
    const float* w_qkv  = (const float*)d_in[2];
    const float* w_proj = (const float*)d_in[3];
    const float* b_proj = (const float*)d_in[4];
    float*       out    = (float*)d_out;

    void *pm, *pxh, *pxl, *pqh, *pql, *pph, *ppl, *pkv, *pah, *pal;
    cudaGetSymbolAddress(&pm, g_mask);
    cudaGetSymbolAddress(&pxh, g_xhi);  cudaGetSymbolAddress(&pxl, g_xlo);
    cudaGetSymbolAddress(&pqh, g_wqh);  cudaGetSymbolAddress(&pql, g_wql);
    cudaGetSymbolAddress(&pph, g_wph);  cudaGetSymbolAddress(&ppl, g_wpl);
    cudaGetSymbolAddress(&pkv, g_kvh);
    cudaGetSymbolAddress(&pah, g_ath);  cudaGetSymbolAddress(&pal, g_atl);

    uint32_t* msk = (uint32_t*)pm;
    uint16_t* xhi = (uint16_t*)pxh; uint16_t* xlo = (uint16_t*)pxl;
    uint16_t* wqh = (uint16_t*)pqh; uint16_t* wql = (uint16_t*)pql;
    uint16_t* wph = (uint16_t*)pph; uint16_t* wpl = (uint16_t*)ppl;
    uint16_t* kvh = (uint16_t*)pkv;
    uint16_t* ath = (uint16_t*)pah; uint16_t* atl = (uint16_t*)pal;

    // 0) packs (mask + one fused operand pack)
    pack_mask<<<(NTOK * (NTOK / 32)) / 256, 256>>>(adj, msk);
    pack_all<<<ALLG / 256, 256>>>(x, w_qkv, w_proj,
                                  xhi, xlo, wqh, wql, wph, wpl);

    // 1) QKV projection -> fp16 (2-term; q columns pre-scaled)
    {
        dim3 grid(768 / 64, NTOK / 128);
        gemm_tch<<<grid, 256>>>(xhi, xlo, wqh, wql, kvh, NTOK, 3 * CDIM, CDIM);
    }
    // 2) tensor-core masked flash attention (128 rows/CTA)
    {
        dim3 grid(NTOK / 128, HEADS);
        attn_tc<<<grid, 256>>>(kvh, msk, ath, atl);
    }
    // 3) output projection + bias (3-term, f32 out)
    {
        dim3 grid(CDIM / 64, NTOK / 128);
        gemm_tc<<<grid, 256>>>(ath, atl, wph, wpl, b_proj, out,
                               NTOK, CDIM, CDIM);
    }
}